// round 10
// baseline (speedup 1.0000x reference)
#include <cuda_runtime.h>
#include <cuda_fp16.h>

#define NN 100000
#define DD 64
#define EMAX 1700000
#define SCAN_CHUNK 1024
#define NSCAN ((NN + SCAN_CHUNK - 1) / SCAN_CHUNK)   // 98
#define ESM_CAP 768

// ----- scratch (device globals; no allocations allowed) -----
// g_cnt is zero at process start (BSS) and k_scan re-zeroes it each call.
__device__ int g_cnt[NN];
__device__ int g_rowptr[NN + 1];
__device__ unsigned short g_rank[EMAX];          // rank of edge within its row
__device__ int g_scan_status[NSCAN];   // 0=empty 1=aggregate 2=prefix
__device__ int g_scan_val[NSCAN];
__device__ int g_scan_incl[NSCAN];
__device__ __align__(16) __half g_xh[NN * DD];   // fp16 copy of x (gather operand)
__device__ __align__(16) __half g_h[NN * DD];    // fp16 SpMM result
__device__ __align__(16) float g_y[NN * DD];
__device__ __align__(16) int2 g_edge[EMAX];      // packed (col*16, val-bits)
__device__ float g_stats[128];                   // [0:64) sum, [64:128) sumsq

// ---------------------------------------------------------------------------
// K1: histogram (rank = atomic return) + fp16 conversion of x + zeroing.
__global__ void k_hist(const float* __restrict__ x,
                       const int* __restrict__ row, int E) {
    int gid = blockIdx.x * blockDim.x + threadIdx.x;
    int stride = gridDim.x * blockDim.x;
    if (gid < 128) g_stats[gid] = 0.0f;
    if (gid < NSCAN) g_scan_status[gid] = 0;

    const float4* x4 = (const float4*)x;
    uint2* xh2 = (uint2*)g_xh;
    for (int i = gid; i < NN * DD / 4; i += stride) {
        float4 v = x4[i];
        __half2 a = __floats2half2_rn(v.x, v.y);
        __half2 c = __floats2half2_rn(v.z, v.w);
        xh2[i] = make_uint2(*reinterpret_cast<unsigned*>(&a),
                            *reinterpret_cast<unsigned*>(&c));
    }

    for (int e = gid; e < E; e += stride)
        g_rank[e] = (unsigned short)atomicAdd(&g_cnt[row[e]], 1);
}

// ---------------------------------------------------------------------------
// K2: single-pass exclusive scan (decoupled lookback) -> rowptr.
__global__ void k_scan(int E) {
    __shared__ int wsum[8];
    __shared__ int s_excl;
    int b = blockIdx.x, t = threadIdx.x;
    int base = b * SCAN_CHUNK + t * 4;
    int v0 = (base + 0 < NN) ? g_cnt[base + 0] : 0;
    int v1 = (base + 1 < NN) ? g_cnt[base + 1] : 0;
    int v2 = (base + 2 < NN) ? g_cnt[base + 2] : 0;
    int v3 = (base + 3 < NN) ? g_cnt[base + 3] : 0;
    if (base + 0 < NN) g_cnt[base + 0] = 0;
    if (base + 1 < NN) g_cnt[base + 1] = 0;
    if (base + 2 < NN) g_cnt[base + 2] = 0;
    if (base + 3 < NN) g_cnt[base + 3] = 0;
    int tsum = v0 + v1 + v2 + v3;
    int lane = t & 31, wid = t >> 5;
    int incl = tsum;
    #pragma unroll
    for (int d = 1; d < 32; d <<= 1) {
        int n = __shfl_up_sync(0xffffffffu, incl, d);
        if (lane >= d) incl += n;
    }
    if (lane == 31) wsum[wid] = incl;
    __syncthreads();
    if (wid == 0) {
        int ws = (lane < 8) ? wsum[lane] : 0;
        #pragma unroll
        for (int d = 1; d < 8; d <<= 1) {
            int n = __shfl_up_sync(0xffffffffu, ws, d);
            if (lane >= d) ws += n;
        }
        if (lane < 8) wsum[lane] = ws;
    }
    __syncthreads();
    int total = wsum[7];

    if (t == 0) {
        g_scan_val[b] = total;
        __threadfence();
        atomicExch(&g_scan_status[b], 1);
    }

    if (wid == 0) {
        int sum = 0;
        int look = b;
        while (look > 0) {
            int idx = look - 32 + lane;
            int st;
            do {
                st = (idx >= 0) ? ((volatile int*)g_scan_status)[idx] : 2;
            } while (__any_sync(0xffffffffu, st == 0));
            __threadfence();
            unsigned pref2 = __ballot_sync(0xffffffffu, (st == 2) && (idx >= 0));
            int contrib = 0;
            if (pref2) {
                int hi = 31 - __clz(pref2);
                if (idx >= 0) {
                    if (lane > hi)       contrib = ((volatile int*)g_scan_val)[idx];
                    else if (lane == hi) contrib = ((volatile int*)g_scan_incl)[idx];
                }
            } else {
                if (idx >= 0) contrib = ((volatile int*)g_scan_val)[idx];
            }
            #pragma unroll
            for (int d = 16; d; d >>= 1)
                contrib += __shfl_xor_sync(0xffffffffu, contrib, d);
            sum += contrib;
            if (pref2) break;
            look -= 32;
        }
        if (lane == 0) {
            s_excl = sum;
            g_scan_incl[b] = sum + total;
            __threadfence();
            atomicExch(&g_scan_status[b], 2);
        }
    }
    __syncthreads();

    int off = s_excl;
    int woff = (wid > 0) ? wsum[wid - 1] : 0;
    int e0 = off + woff + incl - tsum;
    if (base + 0 < NN) g_rowptr[base + 0] = e0;
    if (base + 1 < NN) g_rowptr[base + 1] = e0 + v0;
    if (base + 2 < NN) g_rowptr[base + 2] = e0 + v0 + v1;
    if (base + 3 < NN) g_rowptr[base + 3] = e0 + v0 + v1 + v2;
    if (b == 0 && t == 0) g_rowptr[NN] = E;
}

// ---------------------------------------------------------------------------
// K3: atomic-free scatter: pos = rowptr[row] + rank; store prescaled col*16
__global__ void k_scatter(const int* __restrict__ row,
                          const int* __restrict__ col,
                          const float* __restrict__ val, int E) {
    int gid = blockIdx.x * blockDim.x + threadIdx.x;
    int stride = gridDim.x * blockDim.x;
    for (int e = gid; e < E; e += stride) {
        int r = row[e];
        int pos = g_rowptr[r] + (int)g_rank[e];
        g_edge[pos] = make_int2(col[e] * 16, __float_as_int(val[e]));
    }
}

// ---------------------------------------------------------------------------
// K4: CSR SpMM — 16 rows/block, edges staged once (coalesced) in smem;
// inner loop is LDS-broadcast + fp16 gather, fp32 accumulation, fp16 out.
__global__ __launch_bounds__(256)
void k_spmm_csr() {
    __shared__ __align__(16) int2 esm[ESM_CAP];
    __shared__ int srp[17];
    const uint2* xh2 = (const uint2*)g_xh;    // 16 uint2 per row
    uint2* h2 = (uint2*)g_h;
    int t = threadIdx.x;
    int l = t & 15;               // 4-half column chunk
    int sub = t >> 4;             // row within block (0..15)
    int row0 = blockIdx.x * 16;
    int r = row0 + sub;

    if (t <= 16) {
        int rr = row0 + t;
        srp[t] = g_rowptr[rr <= NN ? rr : NN];
    }
    __syncthreads();
    int start = srp[0];
    int bend = srp[16];
    int n = bend - start;

    float4 acc = make_float4(0.f, 0.f, 0.f, 0.f);
    bool valid = (r < NN);
    int rs = valid ? srp[sub] : 0;
    int re = valid ? srp[sub + 1] : 0;

    if (n <= ESM_CAP) {
        // cooperative coalesced edge load
        for (int i = t; i < n; i += 256)
            esm[i] = g_edge[start + i];
        __syncthreads();
        int e = rs - start, end = re - start;
        for (; e + 4 <= end; e += 4) {
            int2 ed0 = esm[e + 0], ed1 = esm[e + 1];
            int2 ed2 = esm[e + 2], ed3 = esm[e + 3];
            uint2 q0 = xh2[ed0.x + l];
            uint2 q1 = xh2[ed1.x + l];
            uint2 q2 = xh2[ed2.x + l];
            uint2 q3 = xh2[ed3.x + l];
            float v0 = __int_as_float(ed0.y), v1 = __int_as_float(ed1.y);
            float v2 = __int_as_float(ed2.y), v3 = __int_as_float(ed3.y);
            float2 a0 = __half22float2(*reinterpret_cast<__half2*>(&q0.x));
            float2 b0 = __half22float2(*reinterpret_cast<__half2*>(&q0.y));
            float2 a1 = __half22float2(*reinterpret_cast<__half2*>(&q1.x));
            float2 b1 = __half22float2(*reinterpret_cast<__half2*>(&q1.y));
            float2 a2 = __half22float2(*reinterpret_cast<__half2*>(&q2.x));
            float2 b2 = __half22float2(*reinterpret_cast<__half2*>(&q2.y));
            float2 a3 = __half22float2(*reinterpret_cast<__half2*>(&q3.x));
            float2 b3 = __half22float2(*reinterpret_cast<__half2*>(&q3.y));
            acc.x = fmaf(v0, a0.x, acc.x); acc.y = fmaf(v0, a0.y, acc.y);
            acc.z = fmaf(v0, b0.x, acc.z); acc.w = fmaf(v0, b0.y, acc.w);
            acc.x = fmaf(v1, a1.x, acc.x); acc.y = fmaf(v1, a1.y, acc.y);
            acc.z = fmaf(v1, b1.x, acc.z); acc.w = fmaf(v1, b1.y, acc.w);
            acc.x = fmaf(v2, a2.x, acc.x); acc.y = fmaf(v2, a2.y, acc.y);
            acc.z = fmaf(v2, b2.x, acc.z); acc.w = fmaf(v2, b2.y, acc.w);
            acc.x = fmaf(v3, a3.x, acc.x); acc.y = fmaf(v3, a3.y, acc.y);
            acc.z = fmaf(v3, b3.x, acc.z); acc.w = fmaf(v3, b3.y, acc.w);
        }
        for (; e < end; e++) {
            int2 ed = esm[e];
            uint2 q = xh2[ed.x + l];
            float v = __int_as_float(ed.y);
            float2 a = __half22float2(*reinterpret_cast<__half2*>(&q.x));
            float2 bq = __half22float2(*reinterpret_cast<__half2*>(&q.y));
            acc.x = fmaf(v, a.x, acc.x); acc.y = fmaf(v, a.y, acc.y);
            acc.z = fmaf(v, bq.x, acc.z); acc.w = fmaf(v, bq.y, acc.w);
        }
    } else {
        // fallback: direct global reads (never expected for this distribution)
        for (int e = rs; e < re; e++) {
            int2 ed = g_edge[e];
            uint2 q = xh2[ed.x + l];
            float v = __int_as_float(ed.y);
            float2 a = __half22float2(*reinterpret_cast<__half2*>(&q.x));
            float2 bq = __half22float2(*reinterpret_cast<__half2*>(&q.y));
            acc.x = fmaf(v, a.x, acc.x); acc.y = fmaf(v, a.y, acc.y);
            acc.z = fmaf(v, bq.x, acc.z); acc.w = fmaf(v, bq.y, acc.w);
        }
    }

    if (valid) {
        __half2 o0 = __floats2half2_rn(acc.x, acc.y);
        __half2 o1 = __floats2half2_rn(acc.z, acc.w);
        h2[r * 16 + l] = make_uint2(*reinterpret_cast<unsigned*>(&o0),
                                    *reinterpret_cast<unsigned*>(&o1));
    }
}

// ---------------------------------------------------------------------------
// K5: y = h @ W^T + b + x, fused BN statistics (register-blocked 4x4)
__global__ void k_gemm_stats(const float* __restrict__ x,
                             const float* __restrict__ W,
                             const float* __restrict__ b) {
    __shared__ float wts[64 * 68];   // W transposed: wts[in*68 + o]
    __shared__ float hsm[64 * 68];   // h rows (fp32): hsm[rl*68 + in]
    __shared__ float ssm[64], qsm[64];
    int t = threadIdx.x;
    for (int i = t; i < 4096; i += 256) {
        int o = i >> 6, in = i & 63;
        wts[in * 68 + o] = W[i];
    }
    if (t < 64) { ssm[t] = 0.f; qsm[t] = 0.f; }

    int l = t & 15, g = t >> 4;
    int row0 = blockIdx.x * 64;

    const uint2* h2g = (const uint2*)g_h;      // 16 uint2 per row
    for (int i = t; i < 1024; i += 256) {
        int rl = i >> 4, c4 = i & 15;
        int r = row0 + rl;
        uint2 q = (r < NN) ? h2g[r * 16 + c4] : make_uint2(0u, 0u);
        float2 a = __half22float2(*reinterpret_cast<__half2*>(&q.x));
        float2 c = __half22float2(*reinterpret_cast<__half2*>(&q.y));
        float* dst = hsm + rl * 68 + c4 * 4;
        dst[0] = a.x; dst[1] = a.y; dst[2] = c.x; dst[3] = c.y;
    }
    __syncthreads();

    float4 bias = ((const float4*)b)[l];
    float4 acc0 = bias, acc1 = bias, acc2 = bias, acc3 = bias;
    const float4* wts4 = (const float4*)wts;   // row stride = 17 float4
    int hb = (4 * g) * 68;
    #pragma unroll 8
    for (int in = 0; in < 64; in++) {
        float4 w4 = wts4[in * 17 + l];
        float h0 = hsm[hb + in];
        float h1 = hsm[hb + 68 + in];
        float h2v = hsm[hb + 136 + in];
        float h3 = hsm[hb + 204 + in];
        acc0.x = fmaf(w4.x, h0, acc0.x); acc0.y = fmaf(w4.y, h0, acc0.y);
        acc0.z = fmaf(w4.z, h0, acc0.z); acc0.w = fmaf(w4.w, h0, acc0.w);
        acc1.x = fmaf(w4.x, h1, acc1.x); acc1.y = fmaf(w4.y, h1, acc1.y);
        acc1.z = fmaf(w4.z, h1, acc1.z); acc1.w = fmaf(w4.w, h1, acc1.w);
        acc2.x = fmaf(w4.x, h2v, acc2.x); acc2.y = fmaf(w4.y, h2v, acc2.y);
        acc2.z = fmaf(w4.z, h2v, acc2.z); acc2.w = fmaf(w4.w, h2v, acc2.w);
        acc3.x = fmaf(w4.x, h3, acc3.x); acc3.y = fmaf(w4.y, h3, acc3.y);
        acc3.z = fmaf(w4.z, h3, acc3.z); acc3.w = fmaf(w4.w, h3, acc3.w);
    }

    const float4* x4g = (const float4*)x;
    float4* y4 = (float4*)g_y;
    float4 s4 = make_float4(0.f, 0.f, 0.f, 0.f);
    float4 q4 = make_float4(0.f, 0.f, 0.f, 0.f);
    int r0 = row0 + 4 * g;
    float4 accs[4] = {acc0, acc1, acc2, acc3};
    #pragma unroll
    for (int ni = 0; ni < 4; ni++) {
        int r = r0 + ni;
        if (r < NN) {
            float4 xv = x4g[r * 16 + l];
            float4 a = accs[ni];
            a.x += xv.x; a.y += xv.y; a.z += xv.z; a.w += xv.w;
            y4[r * 16 + l] = a;
            s4.x += a.x; s4.y += a.y; s4.z += a.z; s4.w += a.w;
            q4.x = fmaf(a.x, a.x, q4.x); q4.y = fmaf(a.y, a.y, q4.y);
            q4.z = fmaf(a.z, a.z, q4.z); q4.w = fmaf(a.w, a.w, q4.w);
        }
    }
    atomicAdd(&ssm[l * 4 + 0], s4.x); atomicAdd(&ssm[l * 4 + 1], s4.y);
    atomicAdd(&ssm[l * 4 + 2], s4.z); atomicAdd(&ssm[l * 4 + 3], s4.w);
    atomicAdd(&qsm[l * 4 + 0], q4.x); atomicAdd(&qsm[l * 4 + 1], q4.y);
    atomicAdd(&qsm[l * 4 + 2], q4.z); atomicAdd(&qsm[l * 4 + 3], q4.w);
    __syncthreads();
    if (t < 64) {
        atomicAdd(&g_stats[t], ssm[t]);
        atomicAdd(&g_stats[64 + t], qsm[t]);
    }
}

// ---------------------------------------------------------------------------
// K6: out = relu(y * scale + shift); scale/shift derived per-block
__global__ void k_norm(float* __restrict__ out,
                       const float* __restrict__ gamma,
                       const float* __restrict__ beta, int n4) {
    __shared__ float sc[64], sh[64];
    int t = threadIdx.x;
    if (t < 64) {
        float inv_n = 1.0f / (float)NN;
        float mean = g_stats[t] * inv_n;
        float var  = g_stats[64 + t] * inv_n - mean * mean;
        float s = gamma[t] * rsqrtf(var + 1e-5f);
        sc[t] = s;
        sh[t] = beta[t] - mean * s;
    }
    __syncthreads();
    const float4* y4 = reinterpret_cast<const float4*>(g_y);
    float4* o4 = reinterpret_cast<float4*>(out);
    for (int i = blockIdx.x * blockDim.x + t; i < n4;
         i += gridDim.x * blockDim.x) {
        int c4 = (i & 15) * 4;
        float4 v = y4[i];
        v.x = fmaxf(fmaf(v.x, sc[c4 + 0], sh[c4 + 0]), 0.f);
        v.y = fmaxf(fmaf(v.y, sc[c4 + 1], sh[c4 + 1]), 0.f);
        v.z = fmaxf(fmaf(v.z, sc[c4 + 2], sh[c4 + 2]), 0.f);
        v.w = fmaxf(fmaf(v.w, sc[c4 + 3], sh[c4 + 3]), 0.f);
        o4[i] = v;
    }
}

// ---------------------------------------------------------------------------
// inputs (metadata order): x, adj_val, W, b, gamma, beta, adj_row, adj_col
extern "C" void kernel_launch(void* const* d_in, const int* in_sizes, int n_in,
                              void* d_out, int out_size) {
    const float* x       = (const float*)d_in[0];
    const float* adj_val = (const float*)d_in[1];
    const float* W       = (const float*)d_in[2];
    const float* b       = (const float*)d_in[3];
    const float* gamma   = (const float*)d_in[4];
    const float* beta    = (const float*)d_in[5];
    const int*   adj_row = (const int*)d_in[6];
    const int*   adj_col = (const int*)d_in[7];
    float* out = (float*)d_out;
    int E = in_sizes[1];

    int n4 = NN * DD / 4;

    k_hist<<<1184, 256>>>(x, adj_row, E);
    k_scan<<<NSCAN, 256>>>(E);
    k_scatter<<<1184, 256>>>(adj_row, adj_col, adj_val, E);
    k_spmm_csr<<<(NN + 15) / 16, 256>>>();
    k_gemm_stats<<<(NN + 63) / 64, 256>>>(x, W, b);
    k_norm<<<1184, 256>>>(out, gamma, beta, n4);
}

// round 11
// speedup vs baseline: 1.0471x; 1.0471x over previous
#include <cuda_runtime.h>
#include <cuda_fp16.h>

#define NN 100000
#define DD 64
#define EMAX 1700000
#define SCAN_CHUNK 1024
#define NSCAN ((NN + SCAN_CHUNK - 1) / SCAN_CHUNK)   // 98
#define ESM_CAP 768
#define SS_BLOCKS 592

// ----- scratch (device globals; no allocations allowed) -----
// g_cnt is zero at process start (BSS) and k_scan_scatter re-zeroes it.
__device__ int g_cnt[NN];
__device__ int g_rowptr[NN + 1];
__device__ unsigned short g_rank[EMAX];          // rank of edge within its row
__device__ int g_scan_status[NSCAN];   // 0=empty 1=aggregate 2=prefix
__device__ int g_scan_val[NSCAN];
__device__ int g_scan_incl[NSCAN];
__device__ int g_done;                 // #scan blocks that published rowptr
__device__ __align__(16) __half g_xh[NN * DD];   // fp16 copy of x (gather operand)
__device__ __align__(16) __half g_h[NN * DD];    // fp16 SpMM result
__device__ __align__(16) __half g_y[NN * DD];    // fp16 pre-BN activations
__device__ __align__(16) int2 g_edge[EMAX];      // packed (col*16, val-bits)
__device__ float g_stats[128];                   // [0:64) sum, [64:128) sumsq

// ---------------------------------------------------------------------------
// K1: histogram (rank = atomic return) + fp16 conversion of x + zeroing.
__global__ void k_hist(const float* __restrict__ x,
                       const int* __restrict__ row, int E) {
    int gid = blockIdx.x * blockDim.x + threadIdx.x;
    int stride = gridDim.x * blockDim.x;
    if (gid < 128) g_stats[gid] = 0.0f;
    if (gid < NSCAN) g_scan_status[gid] = 0;
    if (gid == 0) g_done = 0;

    const float4* x4 = (const float4*)x;
    uint2* xh2 = (uint2*)g_xh;
    for (int i = gid; i < NN * DD / 4; i += stride) {
        float4 v = x4[i];
        __half2 a = __floats2half2_rn(v.x, v.y);
        __half2 c = __floats2half2_rn(v.z, v.w);
        xh2[i] = make_uint2(*reinterpret_cast<unsigned*>(&a),
                            *reinterpret_cast<unsigned*>(&c));
    }

    for (int e = gid; e < E; e += stride)
        g_rank[e] = (unsigned short)atomicAdd(&g_cnt[row[e]], 1);
}

// ---------------------------------------------------------------------------
// K2: fused scan (decoupled lookback, blocks 0..NSCAN-1) + scatter (all blocks).
// All SS_BLOCKS blocks are co-resident (8 warps each, <=1184 capacity), so
// spinning on g_done cannot deadlock.
__global__ __launch_bounds__(256)
void k_scan_scatter(const int* __restrict__ row,
                    const int* __restrict__ col,
                    const float* __restrict__ val, int E) {
    __shared__ int wsum[8];
    __shared__ int s_excl;
    int b = blockIdx.x, t = threadIdx.x;
    int lane = t & 31, wid = t >> 5;

    if (b < NSCAN) {
        int base = b * SCAN_CHUNK + t * 4;
        int v0 = (base + 0 < NN) ? g_cnt[base + 0] : 0;
        int v1 = (base + 1 < NN) ? g_cnt[base + 1] : 0;
        int v2 = (base + 2 < NN) ? g_cnt[base + 2] : 0;
        int v3 = (base + 3 < NN) ? g_cnt[base + 3] : 0;
        if (base + 0 < NN) g_cnt[base + 0] = 0;
        if (base + 1 < NN) g_cnt[base + 1] = 0;
        if (base + 2 < NN) g_cnt[base + 2] = 0;
        if (base + 3 < NN) g_cnt[base + 3] = 0;
        int tsum = v0 + v1 + v2 + v3;
        int incl = tsum;
        #pragma unroll
        for (int d = 1; d < 32; d <<= 1) {
            int n = __shfl_up_sync(0xffffffffu, incl, d);
            if (lane >= d) incl += n;
        }
        if (lane == 31) wsum[wid] = incl;
        __syncthreads();
        if (wid == 0) {
            int ws = (lane < 8) ? wsum[lane] : 0;
            #pragma unroll
            for (int d = 1; d < 8; d <<= 1) {
                int n = __shfl_up_sync(0xffffffffu, ws, d);
                if (lane >= d) ws += n;
            }
            if (lane < 8) wsum[lane] = ws;
        }
        __syncthreads();
        int total = wsum[7];

        if (t == 0) {
            g_scan_val[b] = total;
            __threadfence();
            atomicExch(&g_scan_status[b], 1);
        }

        if (wid == 0) {
            int sum = 0;
            int look = b;
            while (look > 0) {
                int idx = look - 32 + lane;
                int st;
                do {
                    st = (idx >= 0) ? ((volatile int*)g_scan_status)[idx] : 2;
                } while (__any_sync(0xffffffffu, st == 0));
                __threadfence();
                unsigned pref2 = __ballot_sync(0xffffffffu, (st == 2) && (idx >= 0));
                int contrib = 0;
                if (pref2) {
                    int hi = 31 - __clz(pref2);
                    if (idx >= 0) {
                        if (lane > hi)       contrib = ((volatile int*)g_scan_val)[idx];
                        else if (lane == hi) contrib = ((volatile int*)g_scan_incl)[idx];
                    }
                } else {
                    if (idx >= 0) contrib = ((volatile int*)g_scan_val)[idx];
                }
                #pragma unroll
                for (int d = 16; d; d >>= 1)
                    contrib += __shfl_xor_sync(0xffffffffu, contrib, d);
                sum += contrib;
                if (pref2) break;
                look -= 32;
            }
            if (lane == 0) {
                s_excl = sum;
                g_scan_incl[b] = sum + total;
                __threadfence();
                atomicExch(&g_scan_status[b], 2);
            }
        }
        __syncthreads();

        int off = s_excl;
        int woff = (wid > 0) ? wsum[wid - 1] : 0;
        int e0 = off + woff + incl - tsum;
        if (base + 0 < NN) g_rowptr[base + 0] = e0;
        if (base + 1 < NN) g_rowptr[base + 1] = e0 + v0;
        if (base + 2 < NN) g_rowptr[base + 2] = e0 + v0 + v1;
        if (base + 3 < NN) g_rowptr[base + 3] = e0 + v0 + v1 + v2;
        if (b == 0 && t == 0) g_rowptr[NN] = E;
        __syncthreads();
        if (t == 0) {
            __threadfence();
            atomicAdd(&g_done, 1);
        }
    }

    // ---- barrier: wait until all NSCAN scan blocks published rowptr ----
    if (t == 0) {
        while (((volatile int*)&g_done)[0] < NSCAN) { }
    }
    __syncthreads();
    __threadfence();

    // ---- scatter phase (all blocks) ----
    int gid = b * 256 + t;
    int stride = SS_BLOCKS * 256;
    for (int e = gid; e < E; e += stride) {
        int r = row[e];
        int pos = g_rowptr[r] + (int)g_rank[e];
        g_edge[pos] = make_int2(col[e] * 16, __float_as_int(val[e]));
    }
}

// ---------------------------------------------------------------------------
// K3: CSR SpMM — 16 rows/block, edges staged once (coalesced) in smem;
// inner loop is LDS-broadcast + fp16 gather, fp32 accumulation, fp16 out.
__global__ __launch_bounds__(256)
void k_spmm_csr() {
    __shared__ __align__(16) int2 esm[ESM_CAP];
    __shared__ int srp[17];
    const uint2* xh2 = (const uint2*)g_xh;    // 16 uint2 per row
    uint2* h2 = (uint2*)g_h;
    int t = threadIdx.x;
    int l = t & 15;
    int sub = t >> 4;
    int row0 = blockIdx.x * 16;
    int r = row0 + sub;

    if (t <= 16) {
        int rr = row0 + t;
        srp[t] = g_rowptr[rr <= NN ? rr : NN];
    }
    __syncthreads();
    int start = srp[0];
    int bend = srp[16];
    int n = bend - start;

    float4 acc = make_float4(0.f, 0.f, 0.f, 0.f);
    bool valid = (r < NN);
    int rs = valid ? srp[sub] : 0;
    int re = valid ? srp[sub + 1] : 0;

    if (n <= ESM_CAP) {
        for (int i = t; i < n; i += 256)
            esm[i] = g_edge[start + i];
        __syncthreads();
        int e = rs - start, end = re - start;
        for (; e + 4 <= end; e += 4) {
            int2 ed0 = esm[e + 0], ed1 = esm[e + 1];
            int2 ed2 = esm[e + 2], ed3 = esm[e + 3];
            uint2 q0 = xh2[ed0.x + l];
            uint2 q1 = xh2[ed1.x + l];
            uint2 q2 = xh2[ed2.x + l];
            uint2 q3 = xh2[ed3.x + l];
            float v0 = __int_as_float(ed0.y), v1 = __int_as_float(ed1.y);
            float v2 = __int_as_float(ed2.y), v3 = __int_as_float(ed3.y);
            float2 a0 = __half22float2(*reinterpret_cast<__half2*>(&q0.x));
            float2 b0 = __half22float2(*reinterpret_cast<__half2*>(&q0.y));
            float2 a1 = __half22float2(*reinterpret_cast<__half2*>(&q1.x));
            float2 b1 = __half22float2(*reinterpret_cast<__half2*>(&q1.y));
            float2 a2 = __half22float2(*reinterpret_cast<__half2*>(&q2.x));
            float2 b2 = __half22float2(*reinterpret_cast<__half2*>(&q2.y));
            float2 a3 = __half22float2(*reinterpret_cast<__half2*>(&q3.x));
            float2 b3 = __half22float2(*reinterpret_cast<__half2*>(&q3.y));
            acc.x = fmaf(v0, a0.x, acc.x); acc.y = fmaf(v0, a0.y, acc.y);
            acc.z = fmaf(v0, b0.x, acc.z); acc.w = fmaf(v0, b0.y, acc.w);
            acc.x = fmaf(v1, a1.x, acc.x); acc.y = fmaf(v1, a1.y, acc.y);
            acc.z = fmaf(v1, b1.x, acc.z); acc.w = fmaf(v1, b1.y, acc.w);
            acc.x = fmaf(v2, a2.x, acc.x); acc.y = fmaf(v2, a2.y, acc.y);
            acc.z = fmaf(v2, b2.x, acc.z); acc.w = fmaf(v2, b2.y, acc.w);
            acc.x = fmaf(v3, a3.x, acc.x); acc.y = fmaf(v3, a3.y, acc.y);
            acc.z = fmaf(v3, b3.x, acc.z); acc.w = fmaf(v3, b3.y, acc.w);
        }
        for (; e < end; e++) {
            int2 ed = esm[e];
            uint2 q = xh2[ed.x + l];
            float v = __int_as_float(ed.y);
            float2 a = __half22float2(*reinterpret_cast<__half2*>(&q.x));
            float2 bq = __half22float2(*reinterpret_cast<__half2*>(&q.y));
            acc.x = fmaf(v, a.x, acc.x); acc.y = fmaf(v, a.y, acc.y);
            acc.z = fmaf(v, bq.x, acc.z); acc.w = fmaf(v, bq.y, acc.w);
        }
    } else {
        for (int e = rs; e < re; e++) {
            int2 ed = g_edge[e];
            uint2 q = xh2[ed.x + l];
            float v = __int_as_float(ed.y);
            float2 a = __half22float2(*reinterpret_cast<__half2*>(&q.x));
            float2 bq = __half22float2(*reinterpret_cast<__half2*>(&q.y));
            acc.x = fmaf(v, a.x, acc.x); acc.y = fmaf(v, a.y, acc.y);
            acc.z = fmaf(v, bq.x, acc.z); acc.w = fmaf(v, bq.y, acc.w);
        }
    }

    if (valid) {
        __half2 o0 = __floats2half2_rn(acc.x, acc.y);
        __half2 o1 = __floats2half2_rn(acc.z, acc.w);
        h2[r * 16 + l] = make_uint2(*reinterpret_cast<unsigned*>(&o0),
                                    *reinterpret_cast<unsigned*>(&o1));
    }
}

// ---------------------------------------------------------------------------
// K4: y = h @ W^T + b + x, fused BN statistics (register-blocked 4x4); y fp16
__global__ void k_gemm_stats(const float* __restrict__ x,
                             const float* __restrict__ W,
                             const float* __restrict__ b) {
    __shared__ float wts[64 * 68];   // W transposed: wts[in*68 + o]
    __shared__ float hsm[64 * 68];   // h rows (fp32): hsm[rl*68 + in]
    __shared__ float ssm[64], qsm[64];
    int t = threadIdx.x;
    for (int i = t; i < 4096; i += 256) {
        int o = i >> 6, in = i & 63;
        wts[in * 68 + o] = W[i];
    }
    if (t < 64) { ssm[t] = 0.f; qsm[t] = 0.f; }

    int l = t & 15, g = t >> 4;
    int row0 = blockIdx.x * 64;

    const uint2* h2g = (const uint2*)g_h;      // 16 uint2 per row
    for (int i = t; i < 1024; i += 256) {
        int rl = i >> 4, c4 = i & 15;
        int r = row0 + rl;
        uint2 q = (r < NN) ? h2g[r * 16 + c4] : make_uint2(0u, 0u);
        float2 a = __half22float2(*reinterpret_cast<__half2*>(&q.x));
        float2 c = __half22float2(*reinterpret_cast<__half2*>(&q.y));
        float* dst = hsm + rl * 68 + c4 * 4;
        dst[0] = a.x; dst[1] = a.y; dst[2] = c.x; dst[3] = c.y;
    }
    __syncthreads();

    float4 bias = ((const float4*)b)[l];
    float4 acc0 = bias, acc1 = bias, acc2 = bias, acc3 = bias;
    const float4* wts4 = (const float4*)wts;   // row stride = 17 float4
    int hb = (4 * g) * 68;
    #pragma unroll 8
    for (int in = 0; in < 64; in++) {
        float4 w4 = wts4[in * 17 + l];
        float h0 = hsm[hb + in];
        float h1 = hsm[hb + 68 + in];
        float h2v = hsm[hb + 136 + in];
        float h3 = hsm[hb + 204 + in];
        acc0.x = fmaf(w4.x, h0, acc0.x); acc0.y = fmaf(w4.y, h0, acc0.y);
        acc0.z = fmaf(w4.z, h0, acc0.z); acc0.w = fmaf(w4.w, h0, acc0.w);
        acc1.x = fmaf(w4.x, h1, acc1.x); acc1.y = fmaf(w4.y, h1, acc1.y);
        acc1.z = fmaf(w4.z, h1, acc1.z); acc1.w = fmaf(w4.w, h1, acc1.w);
        acc2.x = fmaf(w4.x, h2v, acc2.x); acc2.y = fmaf(w4.y, h2v, acc2.y);
        acc2.z = fmaf(w4.z, h2v, acc2.z); acc2.w = fmaf(w4.w, h2v, acc2.w);
        acc3.x = fmaf(w4.x, h3, acc3.x); acc3.y = fmaf(w4.y, h3, acc3.y);
        acc3.z = fmaf(w4.z, h3, acc3.z); acc3.w = fmaf(w4.w, h3, acc3.w);
    }

    const float4* x4g = (const float4*)x;
    uint2* y2 = (uint2*)g_y;
    float4 s4 = make_float4(0.f, 0.f, 0.f, 0.f);
    float4 q4 = make_float4(0.f, 0.f, 0.f, 0.f);
    int r0 = row0 + 4 * g;
    float4 accs[4] = {acc0, acc1, acc2, acc3};
    #pragma unroll
    for (int ni = 0; ni < 4; ni++) {
        int r = r0 + ni;
        if (r < NN) {
            float4 xv = x4g[r * 16 + l];
            float4 a = accs[ni];
            a.x += xv.x; a.y += xv.y; a.z += xv.z; a.w += xv.w;
            __half2 o0 = __floats2half2_rn(a.x, a.y);
            __half2 o1 = __floats2half2_rn(a.z, a.w);
            y2[r * 16 + l] = make_uint2(*reinterpret_cast<unsigned*>(&o0),
                                        *reinterpret_cast<unsigned*>(&o1));
            s4.x += a.x; s4.y += a.y; s4.z += a.z; s4.w += a.w;
            q4.x = fmaf(a.x, a.x, q4.x); q4.y = fmaf(a.y, a.y, q4.y);
            q4.z = fmaf(a.z, a.z, q4.z); q4.w = fmaf(a.w, a.w, q4.w);
        }
    }
    atomicAdd(&ssm[l * 4 + 0], s4.x); atomicAdd(&ssm[l * 4 + 1], s4.y);
    atomicAdd(&ssm[l * 4 + 2], s4.z); atomicAdd(&ssm[l * 4 + 3], s4.w);
    atomicAdd(&qsm[l * 4 + 0], q4.x); atomicAdd(&qsm[l * 4 + 1], q4.y);
    atomicAdd(&qsm[l * 4 + 2], q4.z); atomicAdd(&qsm[l * 4 + 3], q4.w);
    __syncthreads();
    if (t < 64) {
        atomicAdd(&g_stats[t], ssm[t]);
        atomicAdd(&g_stats[64 + t], qsm[t]);
    }
}

// ---------------------------------------------------------------------------
// K5: out = relu(y * scale + shift); y read as fp16
__global__ void k_norm(float* __restrict__ out,
                       const float* __restrict__ gamma,
                       const float* __restrict__ beta, int n16) {
    __shared__ float sc[64], sh[64];
    int t = threadIdx.x;
    if (t < 64) {
        float inv_n = 1.0f / (float)NN;
        float mean = g_stats[t] * inv_n;
        float var  = g_stats[64 + t] * inv_n - mean * mean;
        float s = gamma[t] * rsqrtf(var + 1e-5f);
        sc[t] = s;
        sh[t] = beta[t] - mean * s;
    }
    __syncthreads();
    const uint2* y2 = reinterpret_cast<const uint2*>(g_y);
    float4* o4 = reinterpret_cast<float4*>(out);
    for (int i = blockIdx.x * blockDim.x + t; i < n16;
         i += gridDim.x * blockDim.x) {
        int c4 = (i & 15) * 4;
        uint2 q = y2[i];
        float2 a = __half22float2(*reinterpret_cast<__half2*>(&q.x));
        float2 c = __half22float2(*reinterpret_cast<__half2*>(&q.y));
        float4 v;
        v.x = fmaxf(fmaf(a.x, sc[c4 + 0], sh[c4 + 0]), 0.f);
        v.y = fmaxf(fmaf(a.y, sc[c4 + 1], sh[c4 + 1]), 0.f);
        v.z = fmaxf(fmaf(c.x, sc[c4 + 2], sh[c4 + 2]), 0.f);
        v.w = fmaxf(fmaf(c.y, sc[c4 + 3], sh[c4 + 3]), 0.f);
        o4[i] = v;
    }
}

// ---------------------------------------------------------------------------
// inputs (metadata order): x, adj_val, W, b, gamma, beta, adj_row, adj_col
extern "C" void kernel_launch(void* const* d_in, const int* in_sizes, int n_in,
                              void* d_out, int out_size) {
    const float* x       = (const float*)d_in[0];
    const float* adj_val = (const float*)d_in[1];
    const float* W       = (const float*)d_in[2];
    const float* b       = (const float*)d_in[3];
    const float* gamma   = (const float*)d_in[4];
    const float* beta    = (const float*)d_in[5];
    const int*   adj_row = (const int*)d_in[6];
    const int*   adj_col = (const int*)d_in[7];
    float* out = (float*)d_out;
    int E = in_sizes[1];

    int n16 = NN * DD / 4;   // number of 4-half chunks

    k_hist<<<1184, 256>>>(x, adj_row, E);
    k_scan_scatter<<<SS_BLOCKS, 256>>>(adj_row, adj_col, adj_val, E);
    k_spmm_csr<<<(NN + 15) / 16, 256>>>();
    k_gemm_stats<<<(NN + 63) / 64, 256>>>(x, W, b);
    k_norm<<<1184, 256>>>(out, gamma, beta, n16);
}

// round 12
// speedup vs baseline: 1.0474x; 1.0003x over previous
#include <cuda_runtime.h>
#include <cuda_fp16.h>

#define NN 100000
#define DD 64
#define EMAX 1700000
#define SCAN_CHUNK 1024
#define NSCAN ((NN + SCAN_CHUNK - 1) / SCAN_CHUNK)   // 98
#define ESM_CAP 768
#define SS_BLOCKS 592

// ----- scratch (device globals; no allocations allowed) -----
// g_cnt is zero at process start (BSS) and k_scan_scatter re-zeroes it.
__device__ int g_cnt[NN];
__device__ int g_rowptr[NN + 1];
__device__ unsigned short g_rank[EMAX];          // rank of edge within its row
__device__ int g_scan_status[NSCAN];   // 0=empty 1=aggregate 2=prefix
__device__ int g_scan_val[NSCAN];
__device__ int g_scan_incl[NSCAN];
__device__ int g_done;                 // #scan blocks that published rowptr
__device__ __align__(16) __half g_xh[NN * DD];   // fp16 copy of x (gather operand)
__device__ __align__(16) __half g_h[NN * DD];    // fp16 SpMM result
__device__ __align__(16) __half g_y[NN * DD];    // fp16 pre-BN activations
__device__ __align__(16) int2 g_edge[EMAX];      // packed (col*16, val-bits)
__device__ float g_stats[128];                   // [0:64) sum, [64:128) sumsq

// ---------------------------------------------------------------------------
// K1: histogram (rank = atomic return) + fp16 conversion of x + zeroing.
__global__ void k_hist(const float* __restrict__ x,
                       const int* __restrict__ row, int E) {
    int gid = blockIdx.x * blockDim.x + threadIdx.x;
    int stride = gridDim.x * blockDim.x;
    if (gid < 128) g_stats[gid] = 0.0f;
    if (gid < NSCAN) g_scan_status[gid] = 0;
    if (gid == 0) g_done = 0;

    const float4* x4 = (const float4*)x;
    uint2* xh2 = (uint2*)g_xh;
    for (int i = gid; i < NN * DD / 4; i += stride) {
        float4 v = x4[i];
        __half2 a = __floats2half2_rn(v.x, v.y);
        __half2 c = __floats2half2_rn(v.z, v.w);
        xh2[i] = make_uint2(*reinterpret_cast<unsigned*>(&a),
                            *reinterpret_cast<unsigned*>(&c));
    }

    for (int e = gid; e < E; e += stride)
        g_rank[e] = (unsigned short)atomicAdd(&g_cnt[row[e]], 1);
}

// ---------------------------------------------------------------------------
// K2: fused scan (decoupled lookback, blocks 0..NSCAN-1) + scatter (all blocks).
// All SS_BLOCKS blocks are co-resident (8 warps each, <=1184 capacity), so
// spinning on g_done cannot deadlock.
__global__ __launch_bounds__(256)
void k_scan_scatter(const int* __restrict__ row,
                    const int* __restrict__ col,
                    const float* __restrict__ val, int E) {
    __shared__ int wsum[8];
    __shared__ int s_excl;
    int b = blockIdx.x, t = threadIdx.x;
    int lane = t & 31, wid = t >> 5;

    if (b < NSCAN) {
        int base = b * SCAN_CHUNK + t * 4;
        int v0 = (base + 0 < NN) ? g_cnt[base + 0] : 0;
        int v1 = (base + 1 < NN) ? g_cnt[base + 1] : 0;
        int v2 = (base + 2 < NN) ? g_cnt[base + 2] : 0;
        int v3 = (base + 3 < NN) ? g_cnt[base + 3] : 0;
        if (base + 0 < NN) g_cnt[base + 0] = 0;
        if (base + 1 < NN) g_cnt[base + 1] = 0;
        if (base + 2 < NN) g_cnt[base + 2] = 0;
        if (base + 3 < NN) g_cnt[base + 3] = 0;
        int tsum = v0 + v1 + v2 + v3;
        int incl = tsum;
        #pragma unroll
        for (int d = 1; d < 32; d <<= 1) {
            int n = __shfl_up_sync(0xffffffffu, incl, d);
            if (lane >= d) incl += n;
        }
        if (lane == 31) wsum[wid] = incl;
        __syncthreads();
        if (wid == 0) {
            int ws = (lane < 8) ? wsum[lane] : 0;
            #pragma unroll
            for (int d = 1; d < 8; d <<= 1) {
                int n = __shfl_up_sync(0xffffffffu, ws, d);
                if (lane >= d) ws += n;
            }
            if (lane < 8) wsum[lane] = ws;
        }
        __syncthreads();
        int total = wsum[7];

        if (t == 0) {
            g_scan_val[b] = total;
            __threadfence();
            atomicExch(&g_scan_status[b], 1);
        }

        if (wid == 0) {
            int sum = 0;
            int look = b;
            while (look > 0) {
                int idx = look - 32 + lane;
                int st;
                do {
                    st = (idx >= 0) ? ((volatile int*)g_scan_status)[idx] : 2;
                } while (__any_sync(0xffffffffu, st == 0));
                __threadfence();
                unsigned pref2 = __ballot_sync(0xffffffffu, (st == 2) && (idx >= 0));
                int contrib = 0;
                if (pref2) {
                    int hi = 31 - __clz(pref2);
                    if (idx >= 0) {
                        if (lane > hi)       contrib = ((volatile int*)g_scan_val)[idx];
                        else if (lane == hi) contrib = ((volatile int*)g_scan_incl)[idx];
                    }
                } else {
                    if (idx >= 0) contrib = ((volatile int*)g_scan_val)[idx];
                }
                #pragma unroll
                for (int d = 16; d; d >>= 1)
                    contrib += __shfl_xor_sync(0xffffffffu, contrib, d);
                sum += contrib;
                if (pref2) break;
                look -= 32;
            }
            if (lane == 0) {
                s_excl = sum;
                g_scan_incl[b] = sum + total;
                __threadfence();
                atomicExch(&g_scan_status[b], 2);
            }
        }
        __syncthreads();

        int off = s_excl;
        int woff = (wid > 0) ? wsum[wid - 1] : 0;
        int e0 = off + woff + incl - tsum;
        if (base + 0 < NN) g_rowptr[base + 0] = e0;
        if (base + 1 < NN) g_rowptr[base + 1] = e0 + v0;
        if (base + 2 < NN) g_rowptr[base + 2] = e0 + v0 + v1;
        if (base + 3 < NN) g_rowptr[base + 3] = e0 + v0 + v1 + v2;
        if (b == 0 && t == 0) g_rowptr[NN] = E;
        __syncthreads();
        if (t == 0) {
            __threadfence();
            atomicAdd(&g_done, 1);
        }
    }

    // ---- barrier: wait until all NSCAN scan blocks published rowptr ----
    if (t == 0) {
        while (((volatile int*)&g_done)[0] < NSCAN) { }
    }
    __syncthreads();
    __threadfence();

    // ---- scatter phase (all blocks) ----
    int gid = b * 256 + t;
    int stride = SS_BLOCKS * 256;
    for (int e = gid; e < E; e += stride) {
        int r = row[e];
        int pos = g_rowptr[r] + (int)g_rank[e];
        g_edge[pos] = make_int2(col[e] * 16, __float_as_int(val[e]));
    }
}

// ---------------------------------------------------------------------------
// K3: CSR SpMM — 16 rows/block, edges staged once (coalesced) in smem;
// inner loop is LDS-broadcast + fp16 gather, fp32 accumulation, fp16 out.
__global__ __launch_bounds__(256)
void k_spmm_csr() {
    __shared__ __align__(16) int2 esm[ESM_CAP];
    __shared__ int srp[17];
    const uint2* xh2 = (const uint2*)g_xh;    // 16 uint2 per row
    uint2* h2 = (uint2*)g_h;
    int t = threadIdx.x;
    int l = t & 15;
    int sub = t >> 4;
    int row0 = blockIdx.x * 16;
    int r = row0 + sub;

    if (t <= 16) {
        int rr = row0 + t;
        srp[t] = g_rowptr[rr <= NN ? rr : NN];
    }
    __syncthreads();
    int start = srp[0];
    int bend = srp[16];
    int n = bend - start;

    float4 acc = make_float4(0.f, 0.f, 0.f, 0.f);
    bool valid = (r < NN);
    int rs = valid ? srp[sub] : 0;
    int re = valid ? srp[sub + 1] : 0;

    if (n <= ESM_CAP) {
        for (int i = t; i < n; i += 256)
            esm[i] = g_edge[start + i];
        __syncthreads();
        int e = rs - start, end = re - start;
        for (; e + 4 <= end; e += 4) {
            int2 ed0 = esm[e + 0], ed1 = esm[e + 1];
            int2 ed2 = esm[e + 2], ed3 = esm[e + 3];
            uint2 q0 = xh2[ed0.x + l];
            uint2 q1 = xh2[ed1.x + l];
            uint2 q2 = xh2[ed2.x + l];
            uint2 q3 = xh2[ed3.x + l];
            float v0 = __int_as_float(ed0.y), v1 = __int_as_float(ed1.y);
            float v2 = __int_as_float(ed2.y), v3 = __int_as_float(ed3.y);
            float2 a0 = __half22float2(*reinterpret_cast<__half2*>(&q0.x));
            float2 b0 = __half22float2(*reinterpret_cast<__half2*>(&q0.y));
            float2 a1 = __half22float2(*reinterpret_cast<__half2*>(&q1.x));
            float2 b1 = __half22float2(*reinterpret_cast<__half2*>(&q1.y));
            float2 a2 = __half22float2(*reinterpret_cast<__half2*>(&q2.x));
            float2 b2 = __half22float2(*reinterpret_cast<__half2*>(&q2.y));
            float2 a3 = __half22float2(*reinterpret_cast<__half2*>(&q3.x));
            float2 b3 = __half22float2(*reinterpret_cast<__half2*>(&q3.y));
            acc.x = fmaf(v0, a0.x, acc.x); acc.y = fmaf(v0, a0.y, acc.y);
            acc.z = fmaf(v0, b0.x, acc.z); acc.w = fmaf(v0, b0.y, acc.w);
            acc.x = fmaf(v1, a1.x, acc.x); acc.y = fmaf(v1, a1.y, acc.y);
            acc.z = fmaf(v1, b1.x, acc.z); acc.w = fmaf(v1, b1.y, acc.w);
            acc.x = fmaf(v2, a2.x, acc.x); acc.y = fmaf(v2, a2.y, acc.y);
            acc.z = fmaf(v2, b2.x, acc.z); acc.w = fmaf(v2, b2.y, acc.w);
            acc.x = fmaf(v3, a3.x, acc.x); acc.y = fmaf(v3, a3.y, acc.y);
            acc.z = fmaf(v3, b3.x, acc.z); acc.w = fmaf(v3, b3.y, acc.w);
        }
        for (; e < end; e++) {
            int2 ed = esm[e];
            uint2 q = xh2[ed.x + l];
            float v = __int_as_float(ed.y);
            float2 a = __half22float2(*reinterpret_cast<__half2*>(&q.x));
            float2 bq = __half22float2(*reinterpret_cast<__half2*>(&q.y));
            acc.x = fmaf(v, a.x, acc.x); acc.y = fmaf(v, a.y, acc.y);
            acc.z = fmaf(v, bq.x, acc.z); acc.w = fmaf(v, bq.y, acc.w);
        }
    } else {
        for (int e = rs; e < re; e++) {
            int2 ed = g_edge[e];
            uint2 q = xh2[ed.x + l];
            float v = __int_as_float(ed.y);
            float2 a = __half22float2(*reinterpret_cast<__half2*>(&q.x));
            float2 bq = __half22float2(*reinterpret_cast<__half2*>(&q.y));
            acc.x = fmaf(v, a.x, acc.x); acc.y = fmaf(v, a.y, acc.y);
            acc.z = fmaf(v, bq.x, acc.z); acc.w = fmaf(v, bq.y, acc.w);
        }
    }

    if (valid) {
        __half2 o0 = __floats2half2_rn(acc.x, acc.y);
        __half2 o1 = __floats2half2_rn(acc.z, acc.w);
        h2[r * 16 + l] = make_uint2(*reinterpret_cast<unsigned*>(&o0),
                                    *reinterpret_cast<unsigned*>(&o1));
    }
}

// ---------------------------------------------------------------------------
// K4: y = h @ W^T + b + x, fused BN statistics (register-blocked 4x4); y fp16
__global__ void k_gemm_stats(const float* __restrict__ x,
                             const float* __restrict__ W,
                             const float* __restrict__ b) {
    __shared__ float wts[64 * 68];   // W transposed: wts[in*68 + o]
    __shared__ float hsm[64 * 68];   // h rows (fp32): hsm[rl*68 + in]
    __shared__ float ssm[64], qsm[64];
    int t = threadIdx.x;
    for (int i = t; i < 4096; i += 256) {
        int o = i >> 6, in = i & 63;
        wts[in * 68 + o] = W[i];
    }
    if (t < 64) { ssm[t] = 0.f; qsm[t] = 0.f; }

    int l = t & 15, g = t >> 4;
    int row0 = blockIdx.x * 64;

    const uint2* h2g = (const uint2*)g_h;      // 16 uint2 per row
    for (int i = t; i < 1024; i += 256) {
        int rl = i >> 4, c4 = i & 15;
        int r = row0 + rl;
        uint2 q = (r < NN) ? h2g[r * 16 + c4] : make_uint2(0u, 0u);
        float2 a = __half22float2(*reinterpret_cast<__half2*>(&q.x));
        float2 c = __half22float2(*reinterpret_cast<__half2*>(&q.y));
        float* dst = hsm + rl * 68 + c4 * 4;
        dst[0] = a.x; dst[1] = a.y; dst[2] = c.x; dst[3] = c.y;
    }
    __syncthreads();

    float4 bias = ((const float4*)b)[l];
    float4 acc0 = bias, acc1 = bias, acc2 = bias, acc3 = bias;
    const float4* wts4 = (const float4*)wts;   // row stride = 17 float4
    int hb = (4 * g) * 68;
    #pragma unroll 8
    for (int in = 0; in < 64; in++) {
        float4 w4 = wts4[in * 17 + l];
        float h0 = hsm[hb + in];
        float h1 = hsm[hb + 68 + in];
        float h2v = hsm[hb + 136 + in];
        float h3 = hsm[hb + 204 + in];
        acc0.x = fmaf(w4.x, h0, acc0.x); acc0.y = fmaf(w4.y, h0, acc0.y);
        acc0.z = fmaf(w4.z, h0, acc0.z); acc0.w = fmaf(w4.w, h0, acc0.w);
        acc1.x = fmaf(w4.x, h1, acc1.x); acc1.y = fmaf(w4.y, h1, acc1.y);
        acc1.z = fmaf(w4.z, h1, acc1.z); acc1.w = fmaf(w4.w, h1, acc1.w);
        acc2.x = fmaf(w4.x, h2v, acc2.x); acc2.y = fmaf(w4.y, h2v, acc2.y);
        acc2.z = fmaf(w4.z, h2v, acc2.z); acc2.w = fmaf(w4.w, h2v, acc2.w);
        acc3.x = fmaf(w4.x, h3, acc3.x); acc3.y = fmaf(w4.y, h3, acc3.y);
        acc3.z = fmaf(w4.z, h3, acc3.z); acc3.w = fmaf(w4.w, h3, acc3.w);
    }

    const float4* x4g = (const float4*)x;
    uint2* y2 = (uint2*)g_y;
    float4 s4 = make_float4(0.f, 0.f, 0.f, 0.f);
    float4 q4 = make_float4(0.f, 0.f, 0.f, 0.f);
    int r0 = row0 + 4 * g;
    float4 accs[4] = {acc0, acc1, acc2, acc3};
    #pragma unroll
    for (int ni = 0; ni < 4; ni++) {
        int r = r0 + ni;
        if (r < NN) {
            float4 xv = x4g[r * 16 + l];
            float4 a = accs[ni];
            a.x += xv.x; a.y += xv.y; a.z += xv.z; a.w += xv.w;
            __half2 o0 = __floats2half2_rn(a.x, a.y);
            __half2 o1 = __floats2half2_rn(a.z, a.w);
            y2[r * 16 + l] = make_uint2(*reinterpret_cast<unsigned*>(&o0),
                                        *reinterpret_cast<unsigned*>(&o1));
            s4.x += a.x; s4.y += a.y; s4.z += a.z; s4.w += a.w;
            q4.x = fmaf(a.x, a.x, q4.x); q4.y = fmaf(a.y, a.y, q4.y);
            q4.z = fmaf(a.z, a.z, q4.z); q4.w = fmaf(a.w, a.w, q4.w);
        }
    }
    atomicAdd(&ssm[l * 4 + 0], s4.x); atomicAdd(&ssm[l * 4 + 1], s4.y);
    atomicAdd(&ssm[l * 4 + 2], s4.z); atomicAdd(&ssm[l * 4 + 3], s4.w);
    atomicAdd(&qsm[l * 4 + 0], q4.x); atomicAdd(&qsm[l * 4 + 1], q4.y);
    atomicAdd(&qsm[l * 4 + 2], q4.z); atomicAdd(&qsm[l * 4 + 3], q4.w);
    __syncthreads();
    if (t < 64) {
        atomicAdd(&g_stats[t], ssm[t]);
        atomicAdd(&g_stats[64 + t], qsm[t]);
    }
}

// ---------------------------------------------------------------------------
// K5: out = relu(y * scale + shift); y read as fp16
__global__ void k_norm(float* __restrict__ out,
                       const float* __restrict__ gamma,
                       const float* __restrict__ beta, int n16) {
    __shared__ float sc[64], sh[64];
    int t = threadIdx.x;
    if (t < 64) {
        float inv_n = 1.0f / (float)NN;
        float mean = g_stats[t] * inv_n;
        float var  = g_stats[64 + t] * inv_n - mean * mean;
        float s = gamma[t] * rsqrtf(var + 1e-5f);
        sc[t] = s;
        sh[t] = beta[t] - mean * s;
    }
    __syncthreads();
    const uint2* y2 = reinterpret_cast<const uint2*>(g_y);
    float4* o4 = reinterpret_cast<float4*>(out);
    for (int i = blockIdx.x * blockDim.x + t; i < n16;
         i += gridDim.x * blockDim.x) {
        int c4 = (i & 15) * 4;
        uint2 q = y2[i];
        float2 a = __half22float2(*reinterpret_cast<__half2*>(&q.x));
        float2 c = __half22float2(*reinterpret_cast<__half2*>(&q.y));
        float4 v;
        v.x = fmaxf(fmaf(a.x, sc[c4 + 0], sh[c4 + 0]), 0.f);
        v.y = fmaxf(fmaf(a.y, sc[c4 + 1], sh[c4 + 1]), 0.f);
        v.z = fmaxf(fmaf(c.x, sc[c4 + 2], sh[c4 + 2]), 0.f);
        v.w = fmaxf(fmaf(c.y, sc[c4 + 3], sh[c4 + 3]), 0.f);
        o4[i] = v;
    }
}

// ---------------------------------------------------------------------------
// inputs (metadata order): x, adj_val, W, b, gamma, beta, adj_row, adj_col
extern "C" void kernel_launch(void* const* d_in, const int* in_sizes, int n_in,
                              void* d_out, int out_size) {
    const float* x       = (const float*)d_in[0];
    const float* adj_val = (const float*)d_in[1];
    const float* W       = (const float*)d_in[2];
    const float* b       = (const float*)d_in[3];
    const float* gamma   = (const float*)d_in[4];
    const float* beta    = (const float*)d_in[5];
    const int*   adj_row = (const int*)d_in[6];
    const int*   adj_col = (const int*)d_in[7];
    float* out = (float*)d_out;
    int E = in_sizes[1];

    int n16 = NN * DD / 4;   // number of 4-half chunks

    k_hist<<<1184, 256>>>(x, adj_row, E);
    k_scan_scatter<<<SS_BLOCKS, 256>>>(adj_row, adj_col, adj_val, E);
    k_spmm_csr<<<(NN + 15) / 16, 256>>>();
    k_gemm_stats<<<(NN + 63) / 64, 256>>>(x, W, b);
    k_norm<<<1184, 256>>>(out, gamma, beta, n16);
}

// round 13
// speedup vs baseline: 1.1812x; 1.1278x over previous
#include <cuda_runtime.h>
#include <cuda_fp16.h>

#define NN 100000
#define DD 64
#define EMAX 1700000
#define SCAN_CHUNK 1024
#define NSCAN ((NN + SCAN_CHUNK - 1) / SCAN_CHUNK)   // 98
#define ESM_CAP 768
#define SS_BLOCKS 592

// ----- scratch (device globals; no allocations allowed) -----
__device__ int g_cnt[NN];
__device__ int g_rowptr[NN + 1];
__device__ unsigned short g_rank[EMAX];
__device__ int g_scan_status[NSCAN];
__device__ int g_scan_val[NSCAN];
__device__ int g_scan_incl[NSCAN];
__device__ int g_done;
__device__ __align__(16) __half g_xh[NN * DD];
__device__ __align__(16) __half g_h[NN * DD];
__device__ __align__(16) __half g_y[NN * DD];
__device__ __align__(16) int2 g_edge[EMAX];
__device__ float g_stats[128];

// ---------------------------------------------------------------------------
// K1: histogram (rank = atomic return) + fp16 conversion of x + zeroing.
__global__ void k_hist(const float* __restrict__ x,
                       const int* __restrict__ row, int E) {
    int gid = blockIdx.x * blockDim.x + threadIdx.x;
    int stride = gridDim.x * blockDim.x;
    if (gid < 128) g_stats[gid] = 0.0f;
    if (gid < NSCAN) g_scan_status[gid] = 0;
    if (gid == 0) g_done = 0;

    const float4* x4 = (const float4*)x;
    uint2* xh2 = (uint2*)g_xh;
    for (int i = gid; i < NN * DD / 4; i += stride) {
        float4 v = x4[i];
        __half2 a = __floats2half2_rn(v.x, v.y);
        __half2 c = __floats2half2_rn(v.z, v.w);
        xh2[i] = make_uint2(*reinterpret_cast<unsigned*>(&a),
                            *reinterpret_cast<unsigned*>(&c));
    }

    for (int e = gid; e < E; e += stride)
        g_rank[e] = (unsigned short)atomicAdd(&g_cnt[row[e]], 1);
}

// ---------------------------------------------------------------------------
// K2: fused scan (decoupled lookback) + scatter. All SS_BLOCKS co-resident.
__global__ __launch_bounds__(256)
void k_scan_scatter(const int* __restrict__ row,
                    const int* __restrict__ col,
                    const float* __restrict__ val, int E) {
    __shared__ int wsum[8];
    __shared__ int s_excl;
    int b = blockIdx.x, t = threadIdx.x;
    int lane = t & 31, wid = t >> 5;

    if (b < NSCAN) {
        int base = b * SCAN_CHUNK + t * 4;
        int v0 = (base + 0 < NN) ? g_cnt[base + 0] : 0;
        int v1 = (base + 1 < NN) ? g_cnt[base + 1] : 0;
        int v2 = (base + 2 < NN) ? g_cnt[base + 2] : 0;
        int v3 = (base + 3 < NN) ? g_cnt[base + 3] : 0;
        if (base + 0 < NN) g_cnt[base + 0] = 0;
        if (base + 1 < NN) g_cnt[base + 1] = 0;
        if (base + 2 < NN) g_cnt[base + 2] = 0;
        if (base + 3 < NN) g_cnt[base + 3] = 0;
        int tsum = v0 + v1 + v2 + v3;
        int incl = tsum;
        #pragma unroll
        for (int d = 1; d < 32; d <<= 1) {
            int n = __shfl_up_sync(0xffffffffu, incl, d);
            if (lane >= d) incl += n;
        }
        if (lane == 31) wsum[wid] = incl;
        __syncthreads();
        if (wid == 0) {
            int ws = (lane < 8) ? wsum[lane] : 0;
            #pragma unroll
            for (int d = 1; d < 8; d <<= 1) {
                int n = __shfl_up_sync(0xffffffffu, ws, d);
                if (lane >= d) ws += n;
            }
            if (lane < 8) wsum[lane] = ws;
        }
        __syncthreads();
        int total = wsum[7];

        if (t == 0) {
            g_scan_val[b] = total;
            __threadfence();
            atomicExch(&g_scan_status[b], 1);
        }

        if (wid == 0) {
            int sum = 0;
            int look = b;
            while (look > 0) {
                int idx = look - 32 + lane;
                int st;
                do {
                    st = (idx >= 0) ? ((volatile int*)g_scan_status)[idx] : 2;
                } while (__any_sync(0xffffffffu, st == 0));
                __threadfence();
                unsigned pref2 = __ballot_sync(0xffffffffu, (st == 2) && (idx >= 0));
                int contrib = 0;
                if (pref2) {
                    int hi = 31 - __clz(pref2);
                    if (idx >= 0) {
                        if (lane > hi)       contrib = ((volatile int*)g_scan_val)[idx];
                        else if (lane == hi) contrib = ((volatile int*)g_scan_incl)[idx];
                    }
                } else {
                    if (idx >= 0) contrib = ((volatile int*)g_scan_val)[idx];
                }
                #pragma unroll
                for (int d = 16; d; d >>= 1)
                    contrib += __shfl_xor_sync(0xffffffffu, contrib, d);
                sum += contrib;
                if (pref2) break;
                look -= 32;
            }
            if (lane == 0) {
                s_excl = sum;
                g_scan_incl[b] = sum + total;
                __threadfence();
                atomicExch(&g_scan_status[b], 2);
            }
        }
        __syncthreads();

        int off = s_excl;
        int woff = (wid > 0) ? wsum[wid - 1] : 0;
        int e0 = off + woff + incl - tsum;
        if (base + 0 < NN) g_rowptr[base + 0] = e0;
        if (base + 1 < NN) g_rowptr[base + 1] = e0 + v0;
        if (base + 2 < NN) g_rowptr[base + 2] = e0 + v0 + v1;
        if (base + 3 < NN) g_rowptr[base + 3] = e0 + v0 + v1 + v2;
        if (b == 0 && t == 0) g_rowptr[NN] = E;
        __syncthreads();
        if (t == 0) {
            __threadfence();
            atomicAdd(&g_done, 1);
        }
    }

    if (t == 0) {
        while (((volatile int*)&g_done)[0] < NSCAN) { }
    }
    __syncthreads();
    __threadfence();

    int gid = b * 256 + t;
    int stride = SS_BLOCKS * 256;
    for (int e = gid; e < E; e += stride) {
        int r = row[e];
        int pos = g_rowptr[r] + (int)g_rank[e];
        g_edge[pos] = make_int2(col[e] * 16, __float_as_int(val[e]));
    }
}

// ---------------------------------------------------------------------------
// K3: CSR SpMM — 16 rows/block, smem edge staging, fp16 gather, fp32 acc.
__global__ __launch_bounds__(256)
void k_spmm_csr() {
    __shared__ __align__(16) int2 esm[ESM_CAP];
    __shared__ int srp[17];
    const uint2* xh2 = (const uint2*)g_xh;
    uint2* h2 = (uint2*)g_h;
    int t = threadIdx.x;
    int l = t & 15;
    int sub = t >> 4;
    int row0 = blockIdx.x * 16;
    int r = row0 + sub;

    if (t <= 16) {
        int rr = row0 + t;
        srp[t] = g_rowptr[rr <= NN ? rr : NN];
    }
    __syncthreads();
    int start = srp[0];
    int bend = srp[16];
    int n = bend - start;

    float4 acc = make_float4(0.f, 0.f, 0.f, 0.f);
    bool valid = (r < NN);
    int rs = valid ? srp[sub] : 0;
    int re = valid ? srp[sub + 1] : 0;

    if (n <= ESM_CAP) {
        for (int i = t; i < n; i += 256)
            esm[i] = g_edge[start + i];
        __syncthreads();
        int e = rs - start, end = re - start;
        for (; e + 4 <= end; e += 4) {
            int2 ed0 = esm[e + 0], ed1 = esm[e + 1];
            int2 ed2 = esm[e + 2], ed3 = esm[e + 3];
            uint2 q0 = xh2[ed0.x + l];
            uint2 q1 = xh2[ed1.x + l];
            uint2 q2 = xh2[ed2.x + l];
            uint2 q3 = xh2[ed3.x + l];
            float v0 = __int_as_float(ed0.y), v1 = __int_as_float(ed1.y);
            float v2 = __int_as_float(ed2.y), v3 = __int_as_float(ed3.y);
            float2 a0 = __half22float2(*reinterpret_cast<__half2*>(&q0.x));
            float2 b0 = __half22float2(*reinterpret_cast<__half2*>(&q0.y));
            float2 a1 = __half22float2(*reinterpret_cast<__half2*>(&q1.x));
            float2 b1 = __half22float2(*reinterpret_cast<__half2*>(&q1.y));
            float2 a2 = __half22float2(*reinterpret_cast<__half2*>(&q2.x));
            float2 b2 = __half22float2(*reinterpret_cast<__half2*>(&q2.y));
            float2 a3 = __half22float2(*reinterpret_cast<__half2*>(&q3.x));
            float2 b3 = __half22float2(*reinterpret_cast<__half2*>(&q3.y));
            acc.x = fmaf(v0, a0.x, acc.x); acc.y = fmaf(v0, a0.y, acc.y);
            acc.z = fmaf(v0, b0.x, acc.z); acc.w = fmaf(v0, b0.y, acc.w);
            acc.x = fmaf(v1, a1.x, acc.x); acc.y = fmaf(v1, a1.y, acc.y);
            acc.z = fmaf(v1, b1.x, acc.z); acc.w = fmaf(v1, b1.y, acc.w);
            acc.x = fmaf(v2, a2.x, acc.x); acc.y = fmaf(v2, a2.y, acc.y);
            acc.z = fmaf(v2, b2.x, acc.z); acc.w = fmaf(v2, b2.y, acc.w);
            acc.x = fmaf(v3, a3.x, acc.x); acc.y = fmaf(v3, a3.y, acc.y);
            acc.z = fmaf(v3, b3.x, acc.z); acc.w = fmaf(v3, b3.y, acc.w);
        }
        for (; e < end; e++) {
            int2 ed = esm[e];
            uint2 q = xh2[ed.x + l];
            float v = __int_as_float(ed.y);
            float2 a = __half22float2(*reinterpret_cast<__half2*>(&q.x));
            float2 bq = __half22float2(*reinterpret_cast<__half2*>(&q.y));
            acc.x = fmaf(v, a.x, acc.x); acc.y = fmaf(v, a.y, acc.y);
            acc.z = fmaf(v, bq.x, acc.z); acc.w = fmaf(v, bq.y, acc.w);
        }
    } else {
        for (int e = rs; e < re; e++) {
            int2 ed = g_edge[e];
            uint2 q = xh2[ed.x + l];
            float v = __int_as_float(ed.y);
            float2 a = __half22float2(*reinterpret_cast<__half2*>(&q.x));
            float2 bq = __half22float2(*reinterpret_cast<__half2*>(&q.y));
            acc.x = fmaf(v, a.x, acc.x); acc.y = fmaf(v, a.y, acc.y);
            acc.z = fmaf(v, bq.x, acc.z); acc.w = fmaf(v, bq.y, acc.w);
        }
    }

    if (valid) {
        __half2 o0 = __floats2half2_rn(acc.x, acc.y);
        __half2 o1 = __floats2half2_rn(acc.z, acc.w);
        h2[r * 16 + l] = make_uint2(*reinterpret_cast<unsigned*>(&o0),
                                    *reinterpret_cast<unsigned*>(&o1));
    }
}

// ---------------------------------------------------------------------------
// K4: y = h @ W^T + b + x via HMMA; d+bias staged in smem (hsm reuse), then
// coalesced epilogue (residual, fp16 y store, BN stats). 128 nodes / block.
__global__ __launch_bounds__(256)
void k_gemm_stats(const float* __restrict__ x,
                  const float* __restrict__ W,
                  const float* __restrict__ b) {
    __shared__ __half hsm[128 * 72];   // h tile (MMA A); reused for y staging
    __shared__ __half wsm[64 * 72];    // W fp16 (MMA B)
    __shared__ float bsm[64];
    __shared__ float ssm[64], qsm[64];
    int t = threadIdx.x;
    int warp = t >> 5, lane = t & 31;
    int row0 = blockIdx.x * 128;

    for (int i = t; i < 4096; i += 256) {
        int o = i >> 6, in = i & 63;
        wsm[o * 72 + in] = __float2half(W[i]);
    }
    if (t < 64) { bsm[t] = b[t]; ssm[t] = 0.f; qsm[t] = 0.f; }

    const uint2* h2g = (const uint2*)g_h;
    for (int i = t; i < 2048; i += 256) {            // 128 rows x 16 uint2
        int rl = i >> 4, c4 = i & 15;
        int r = row0 + rl;
        uint2 q = (r < NN) ? h2g[r * 16 + c4] : make_uint2(0u, 0u);
        *reinterpret_cast<uint2*>(&hsm[rl * 72 + c4 * 4]) = q;
    }
    __syncthreads();

    int m0 = warp * 16;
    float d[8][4];
    #pragma unroll
    for (int j = 0; j < 8; j++) {
        d[j][0] = 0.f; d[j][1] = 0.f; d[j][2] = 0.f; d[j][3] = 0.f;
    }

    int a_row = m0 + (lane & 7) + 8 * ((lane >> 3) & 1);
    int a_kofs = 8 * (lane >> 4);
    int b_row = lane & 7;
    int b_kofs = 8 * ((lane >> 3) & 1);

    #pragma unroll
    for (int s = 0; s < 4; s++) {
        unsigned a0, a1, a2, a3;
        {
            unsigned saddr = (unsigned)__cvta_generic_to_shared(
                &hsm[a_row * 72 + s * 16 + a_kofs]);
            asm volatile("ldmatrix.sync.aligned.m8n8.x4.shared.b16 "
                         "{%0,%1,%2,%3}, [%4];"
                         : "=r"(a0), "=r"(a1), "=r"(a2), "=r"(a3) : "r"(saddr));
        }
        #pragma unroll
        for (int j = 0; j < 8; j++) {
            unsigned b0, b1;
            unsigned saddr = (unsigned)__cvta_generic_to_shared(
                &wsm[(8 * j + b_row) * 72 + s * 16 + b_kofs]);
            asm volatile("ldmatrix.sync.aligned.m8n8.x2.shared.b16 "
                         "{%0,%1}, [%2];"
                         : "=r"(b0), "=r"(b1) : "r"(saddr));
            asm volatile("mma.sync.aligned.m16n8k16.row.col.f32.f16.f16.f32 "
                         "{%0,%1,%2,%3}, {%4,%5,%6,%7}, {%8,%9}, {%0,%1,%2,%3};"
                         : "+f"(d[j][0]), "+f"(d[j][1]), "+f"(d[j][2]), "+f"(d[j][3])
                         : "r"(a0), "r"(a1), "r"(a2), "r"(a3), "r"(b0), "r"(b1));
        }
    }
    __syncthreads();   // all warps done reading hsm; safe to overwrite with y

    // stage d + bias into hsm as fp16 (layout: [rl*72 + col])
    {
        int gr = lane >> 2, tc = lane & 3;
        int rl0 = m0 + gr, rl1 = rl0 + 8;
        #pragma unroll
        for (int j = 0; j < 8; j++) {
            int o = 8 * j + 2 * tc;
            float bb0 = bsm[o], bb1 = bsm[o + 1];
            __half2 p0 = __floats2half2_rn(d[j][0] + bb0, d[j][1] + bb1);
            __half2 p1 = __floats2half2_rn(d[j][2] + bb0, d[j][3] + bb1);
            *reinterpret_cast<__half2*>(&hsm[rl0 * 72 + o]) = p0;
            *reinterpret_cast<__half2*>(&hsm[rl1 * 72 + o]) = p1;
        }
    }
    __syncthreads();

    // coalesced epilogue: residual + fp16 y store + stats
    const float4* x4g = (const float4*)x;
    uint2* y2 = (uint2*)g_y;
    int l = t & 15;                    // c4 chunk (fixed per thread)
    float4 s4 = make_float4(0.f, 0.f, 0.f, 0.f);
    float4 q4 = make_float4(0.f, 0.f, 0.f, 0.f);
    for (int i = t; i < 2048; i += 256) {
        int rl = i >> 4;
        int r = row0 + rl;
        if (r < NN) {
            uint2 hq = *reinterpret_cast<uint2*>(&hsm[rl * 72 + l * 4]);
            float2 a = __half22float2(*reinterpret_cast<__half2*>(&hq.x));
            float2 c = __half22float2(*reinterpret_cast<__half2*>(&hq.y));
            float4 xv = x4g[r * 16 + l];
            float y0 = a.x + xv.x, y1 = a.y + xv.y;
            float y2v = c.x + xv.z, y3 = c.y + xv.w;
            __half2 o0 = __floats2half2_rn(y0, y1);
            __half2 o1 = __floats2half2_rn(y2v, y3);
            y2[r * 16 + l] = make_uint2(*reinterpret_cast<unsigned*>(&o0),
                                        *reinterpret_cast<unsigned*>(&o1));
            s4.x += y0; s4.y += y1; s4.z += y2v; s4.w += y3;
            q4.x = fmaf(y0, y0, q4.x); q4.y = fmaf(y1, y1, q4.y);
            q4.z = fmaf(y2v, y2v, q4.z); q4.w = fmaf(y3, y3, q4.w);
        }
    }
    atomicAdd(&ssm[l * 4 + 0], s4.x); atomicAdd(&ssm[l * 4 + 1], s4.y);
    atomicAdd(&ssm[l * 4 + 2], s4.z); atomicAdd(&ssm[l * 4 + 3], s4.w);
    atomicAdd(&qsm[l * 4 + 0], q4.x); atomicAdd(&qsm[l * 4 + 1], q4.y);
    atomicAdd(&qsm[l * 4 + 2], q4.z); atomicAdd(&qsm[l * 4 + 3], q4.w);
    __syncthreads();
    if (t < 64) {
        atomicAdd(&g_stats[t], ssm[t]);
        atomicAdd(&g_stats[64 + t], qsm[t]);
    }
}

// ---------------------------------------------------------------------------
// K5: out = relu(y * scale + shift); y read as fp16
__global__ void k_norm(float* __restrict__ out,
                       const float* __restrict__ gamma,
                       const float* __restrict__ beta, int n16) {
    __shared__ float sc[64], sh[64];
    int t = threadIdx.x;
    if (t < 64) {
        float inv_n = 1.0f / (float)NN;
        float mean = g_stats[t] * inv_n;
        float var  = g_stats[64 + t] * inv_n - mean * mean;
        float s = gamma[t] * rsqrtf(var + 1e-5f);
        sc[t] = s;
        sh[t] = beta[t] - mean * s;
    }
    __syncthreads();
    const uint2* y2 = reinterpret_cast<const uint2*>(g_y);
    float4* o4 = reinterpret_cast<float4*>(out);
    for (int i = blockIdx.x * blockDim.x + t; i < n16;
         i += gridDim.x * blockDim.x) {
        int c4 = (i & 15) * 4;
        uint2 q = y2[i];
        float2 a = __half22float2(*reinterpret_cast<__half2*>(&q.x));
        float2 c = __half22float2(*reinterpret_cast<__half2*>(&q.y));
        float4 v;
        v.x = fmaxf(fmaf(a.x, sc[c4 + 0], sh[c4 + 0]), 0.f);
        v.y = fmaxf(fmaf(a.y, sc[c4 + 1], sh[c4 + 1]), 0.f);
        v.z = fmaxf(fmaf(c.x, sc[c4 + 2], sh[c4 + 2]), 0.f);
        v.w = fmaxf(fmaf(c.y, sc[c4 + 3], sh[c4 + 3]), 0.f);
        o4[i] = v;
    }
}

// ---------------------------------------------------------------------------
// inputs (metadata order): x, adj_val, W, b, gamma, beta, adj_row, adj_col
extern "C" void kernel_launch(void* const* d_in, const int* in_sizes, int n_in,
                              void* d_out, int out_size) {
    const float* x       = (const float*)d_in[0];
    const float* adj_val = (const float*)d_in[1];
    const float* W       = (const float*)d_in[2];
    const float* b       = (const float*)d_in[3];
    const float* gamma   = (const float*)d_in[4];
    const float* beta    = (const float*)d_in[5];
    const int*   adj_row = (const int*)d_in[6];
    const int*   adj_col = (const int*)d_in[7];
    float* out = (float*)d_out;
    int E = in_sizes[1];

    int n16 = NN * DD / 4;

    k_hist<<<1184, 256>>>(x, adj_row, E);
    k_scan_scatter<<<SS_BLOCKS, 256>>>(adj_row, adj_col, adj_val, E);
    k_spmm_csr<<<(NN + 15) / 16, 256>>>();
    k_gemm_stats<<<(NN + 127) / 128, 256>>>(x, W, b);
    k_norm<<<1184, 256>>>(out, gamma, beta, n16);
}